// round 8
// baseline (speedup 1.0000x reference)
#include <cuda_runtime.h>
#include <cuda_bf16.h>
#include <cuda_fp16.h>
#include <cstdint>
#include <math.h>

// Problem constants (fixed by the reference setup)
#define N_BATCH 2
#define LQ      16384
#define CDIM    256
#define NH      8
#define NL      4
#define NP      4
#define LIN     21760
#define NGROUP  (N_BATCH*LQ*NH)    // 262144 (n,q,head) groups

// Scratch (device globals; allocation is forbidden)
__device__ __half g_value_h[N_BATCH*LIN*CDIM];   // fp16 projected values
__device__ float  g_off    [N_BATCH*LQ*CDIM];
__device__ float  g_attn   [N_BATCH*LQ*NH*NL*NP];// attn logits
__device__ float  g_sampled[N_BATCH*LQ*CDIM];
// Per-point precomputed gather data (plane-strided SoA: [pi][group])
__device__ int4   g_pidx[16 * NGROUP];           // clamped absolute value-row idx
__device__ float4 g_pw  [16 * NGROUP];           // attn-folded bilinear weights
// Pre-transposed weights, bf16 hi/lo split: [N, K=256] row-major
__device__ __nv_bfloat16 g_wval_hi [CDIM*CDIM], g_wval_lo [CDIM*CDIM];
__device__ __nv_bfloat16 g_woff_hi [CDIM*CDIM], g_woff_lo [CDIM*CDIM];
__device__ __nv_bfloat16 g_wattn_hi[128*CDIM],  g_wattn_lo[128*CDIM];
__device__ __nv_bfloat16 g_wout_hi [CDIM*CDIM], g_wout_lo [CDIM*CDIM];

// ---------------------------------------------------------------------------
// PTX helpers (baseline PTX only — sm_103 non-variant target)
// ---------------------------------------------------------------------------
__device__ __forceinline__ uint32_t smem_u32(const void* p) {
    uint32_t a;
    asm("{ .reg .u64 t; cvta.to.shared.u64 t, %1; cvt.u32.u64 %0, t; }"
        : "=r"(a) : "l"(p));
    return a;
}
__device__ __forceinline__ void ldsm4(uint32_t* r, uint32_t addr) {
    asm volatile("ldmatrix.sync.aligned.m8n8.x4.shared.b16 {%0,%1,%2,%3}, [%4];"
                 : "=r"(r[0]), "=r"(r[1]), "=r"(r[2]), "=r"(r[3]) : "r"(addr));
}
__device__ __forceinline__ void mma16816(float* d, const uint32_t* a, const uint32_t* b) {
    asm volatile(
        "mma.sync.aligned.m16n8k16.row.col.f32.bf16.bf16.f32 "
        "{%0,%1,%2,%3}, {%4,%5,%6,%7}, {%8,%9}, {%0,%1,%2,%3};"
        : "+f"(d[0]), "+f"(d[1]), "+f"(d[2]), "+f"(d[3])
        : "r"(a[0]), "r"(a[1]), "r"(a[2]), "r"(a[3]), "r"(b[0]), "r"(b[1]));
}
#define CP_ASYNC16(dst, src) \
    asm volatile("cp.async.ca.shared.global [%0], [%1], 16;" :: "r"(dst), "l"(src))
#define CP_COMMIT()  asm volatile("cp.async.commit_group;")
#define CP_WAIT0()   asm volatile("cp.async.wait_group 0;" ::: "memory")

// ---------------------------------------------------------------------------
// Fused weight transpose + bf16 hi/lo split (4 weights, one launch)
// ---------------------------------------------------------------------------
__global__ void transpose_all_kernel(
    const float* __restrict__ Wv, const float* __restrict__ Wo,
    const float* __restrict__ Wa, const float* __restrict__ Wu)
{
    const int which = blockIdx.y;
    const int N = (which == 2) ? 128 : 256;
    int idx = blockIdx.x * 256 + threadIdx.x;
    if (idx >= 256 * N) return;
    const float* W = (which == 0) ? Wv : (which == 1) ? Wo : (which == 2) ? Wa : Wu;
    __nv_bfloat16* hi = (which == 0) ? g_wval_hi : (which == 1) ? g_woff_hi
                       : (which == 2) ? g_wattn_hi : g_wout_hi;
    __nv_bfloat16* lo = (which == 0) ? g_wval_lo : (which == 1) ? g_woff_lo
                       : (which == 2) ? g_wattn_lo : g_wout_lo;
    int k = idx / N, n = idx % N;
    float w = W[idx];
    __nv_bfloat16 h = __float2bfloat16(w);
    hi[n * 256 + k] = h;
    lo[n * 256 + k] = __float2bfloat16(w - __bfloat162float(h));
}

// ---------------------------------------------------------------------------
// HMMA GEMM core, bf16x3 split, double-buffered (cp.async B, reg-prefetch A).
// CTA 128x128, BK=32, 8 warps 4x2.
// ---------------------------------------------------------------------------
#define GK       256
#define GBK      32
#define ASTRIDEB 80
#define ABUF     (128 * ASTRIDEB)
#define SMEM_GEMM (8 * ABUF)           // 81920B

template<bool HALF_OUT>
__device__ __forceinline__ void gemm_core(
    const float* __restrict__ A,
    const __nv_bfloat16* __restrict__ Bt_hi,
    const __nv_bfloat16* __restrict__ Bt_lo,
    const float* __restrict__ bias,
    void* __restrict__ Cv, int ldc, int m0, int n0, char* sm)
{
    const uint32_t sb = smem_u32(sm);
    const int tid  = threadIdx.x;
    const int wid  = tid >> 5, lane = tid & 31;
    const int wm   = wid & 3,  wn   = wid >> 2;

    const int frow = tid >> 1;
    const int fkh  = (tid & 1) * 16;

    float acc[2][8][4];
    #pragma unroll
    for (int i = 0; i < 2; i++)
        #pragma unroll
        for (int j = 0; j < 8; j++)
            #pragma unroll
            for (int v = 0; v < 4; v++) acc[i][j][v] = 0.f;

    uint32_t a_addr[2];
    #pragma unroll
    for (int mt = 0; mt < 2; mt++)
        a_addr[mt] = sb + (wm * 32 + mt * 16 + (lane & 15)) * ASTRIDEB
                        + ((lane >> 4) * 8) * 2;
    uint32_t b_addr[4];
    #pragma unroll
    for (int bt = 0; bt < 4; bt++)
        b_addr[bt] = sb + (wn * 64 + bt * 16 + ((lane >> 4) * 8) + (lane & 7)) * ASTRIDEB
                        + (((lane >> 3) & 1) * 8) * 2;

    const float* arow_ptr = A + (size_t)(m0 + frow) * GK + fkh;
    const __nv_bfloat16* bh_ptr = Bt_hi + (size_t)(n0 + frow) * GK + fkh;
    const __nv_bfloat16* bl_ptr = Bt_lo + (size_t)(n0 + frow) * GK + fkh;
    const uint32_t bfill = sb + frow * ASTRIDEB + fkh * 2;

    {
        uint32_t dh = bfill + 4 * ABUF;
        uint32_t dl = dh + ABUF;
        CP_ASYNC16(dh,      bh_ptr);
        CP_ASYNC16(dh + 16, bh_ptr + 8);
        CP_ASYNC16(dl,      bl_ptr);
        CP_ASYNC16(dl + 16, bl_ptr + 8);
        CP_COMMIT();
    }
    float4 va[4];
    #pragma unroll
    for (int j = 0; j < 4; j++) va[j] = ((const float4*)arow_ptr)[j];

    for (int i = 0; i < GK / GBK; i++) {
        const int s = i & 1;
        {
            float v[16];
            #pragma unroll
            for (int j = 0; j < 4; j++) {
                v[j*4+0] = va[j].x; v[j*4+1] = va[j].y;
                v[j*4+2] = va[j].z; v[j*4+3] = va[j].w;
            }
            __nv_bfloat16 h[16], l[16];
            #pragma unroll
            for (int j = 0; j < 16; j++) {
                h[j] = __float2bfloat16(v[j]);
                l[j] = __float2bfloat16(v[j] - __bfloat162float(h[j]));
            }
            char* dh = sm + s * 2 * ABUF + frow * ASTRIDEB + fkh * 2;
            char* dl = dh + ABUF;
            ((uint4*)dh)[0] = ((uint4*)h)[0];  ((uint4*)dh)[1] = ((uint4*)h)[1];
            ((uint4*)dl)[0] = ((uint4*)l)[0];  ((uint4*)dl)[1] = ((uint4*)l)[1];
        }
        if (i < GK / GBK - 1) {
            const float4* nxt = (const float4*)(arow_ptr + (i + 1) * GBK);
            #pragma unroll
            for (int j = 0; j < 4; j++) va[j] = nxt[j];
        }

        CP_WAIT0();
        __syncthreads();

        if (i < GK / GBK - 1) {
            const __nv_bfloat16* sh = bh_ptr + (i + 1) * GBK;
            const __nv_bfloat16* sl = bl_ptr + (i + 1) * GBK;
            uint32_t dh = bfill + 4 * ABUF + (s ^ 1) * 2 * ABUF;
            uint32_t dl = dh + ABUF;
            CP_ASYNC16(dh,      sh);
            CP_ASYNC16(dh + 16, sh + 8);
            CP_ASYNC16(dl,      sl);
            CP_ASYNC16(dl + 16, sl + 8);
            CP_COMMIT();
        }

        const uint32_t aoffS = s * 2 * ABUF;
        const uint32_t boffS = 4 * ABUF + s * 2 * ABUF;
        #pragma unroll
        for (int kk = 0; kk < GBK; kk += 16) {
            const uint32_t ko = kk * 2;
            uint32_t ah[2][4], al[2][4];
            #pragma unroll
            for (int mt = 0; mt < 2; mt++) {
                ldsm4(ah[mt], a_addr[mt] + aoffS + ko);
                ldsm4(al[mt], a_addr[mt] + aoffS + ABUF + ko);
            }
            #pragma unroll
            for (int bt = 0; bt < 4; bt++) {
                uint32_t bh[4], bl[4];
                ldsm4(bh, b_addr[bt] + boffS + ko);
                ldsm4(bl, b_addr[bt] + boffS + ABUF + ko);
                #pragma unroll
                for (int mt = 0; mt < 2; mt++) {
                    float* d0 = acc[mt][bt * 2 + 0];
                    float* d1 = acc[mt][bt * 2 + 1];
                    mma16816(d0, ah[mt], bh + 0);
                    mma16816(d0, ah[mt], bl + 0);
                    mma16816(d0, al[mt], bh + 0);
                    mma16816(d1, ah[mt], bh + 2);
                    mma16816(d1, ah[mt], bl + 2);
                    mma16816(d1, al[mt], bh + 2);
                }
            }
        }
        __syncthreads();
    }

    const int r_in = lane >> 2;
    const int c_in = (lane & 3) * 2;
    #pragma unroll
    for (int mt = 0; mt < 2; mt++) {
        const int rbase = m0 + wm * 32 + mt * 16 + r_in;
        #pragma unroll
        for (int nf = 0; nf < 8; nf++) {
            const int col = n0 + wn * 64 + nf * 8 + c_in;
            const float b0 = bias[col - n0 + n0], b1 = bias[col + 1];
            float* d = acc[mt][nf];
            if (HALF_OUT) {
                __half* C = (__half*)Cv;
                *(__half2*)(C + (size_t)rbase       * ldc + col) =
                    __floats2half2_rn(d[0] + b0, d[1] + b1);
                *(__half2*)(C + (size_t)(rbase + 8) * ldc + col) =
                    __floats2half2_rn(d[2] + b0, d[3] + b1);
            } else {
                float* C = (float*)Cv;
                *(float2*)(C + (size_t)rbase       * ldc + col) = make_float2(d[0] + b0, d[1] + b1);
                *(float2*)(C + (size_t)(rbase + 8) * ldc + col) = make_float2(d[2] + b0, d[3] + b1);
            }
        }
    }
}

template<bool HALF_OUT>
__global__ __launch_bounds__(256, 2) void gemm_mma_kernel(
    const float* __restrict__ A,
    const __nv_bfloat16* __restrict__ Bt_hi,
    const __nv_bfloat16* __restrict__ Bt_lo,
    const float* __restrict__ bias,
    void* __restrict__ Cv, int ldc)
{
    extern __shared__ __align__(16) char sm[];
    gemm_core<HALF_OUT>(A, Bt_hi, Bt_lo, bias, Cv, ldc,
                        blockIdx.x * 128, blockIdx.y * 128, sm);
}

// Merged offset + attn projection: grid.y in {0,1} -> g_off cols, {2} -> g_attn
__global__ __launch_bounds__(256, 2) void gemm_q_kernel(
    const float* __restrict__ query,
    const float* __restrict__ b_off, const float* __restrict__ b_attn,
    float* __restrict__ off_out, float* __restrict__ attn_out)
{
    extern __shared__ __align__(16) char sm[];
    const __nv_bfloat16 *Bh, *Bl;
    const float* bias;
    float* C;
    int ldc, n0;
    if (blockIdx.y < 2) {
        Bh = g_woff_hi;  Bl = g_woff_lo;  bias = b_off;
        C = off_out;  ldc = 256;  n0 = blockIdx.y * 128;
    } else {
        Bh = g_wattn_hi; Bl = g_wattn_lo; bias = b_attn;
        C = attn_out; ldc = 128;  n0 = 0;
    }
    gemm_core<false>(query, Bh, Bl, bias, C, ldc, blockIdx.x * 128, n0, sm);
}

// ---------------------------------------------------------------------------
// Prep: softmax over 16 logits + per-point gather geometry, attn folded into
// bilinear corner weights. One thread per (n,q,head).
// Weight pairing: sample at (l,p) weighted by softmax'd attn[p*4+l]
// (reference pairs p-major values with l-major weights).
// ---------------------------------------------------------------------------
__global__ __launch_bounds__(256) void prep_kernel()
{
    const int t = blockIdx.x * 256 + threadIdx.x;
    if (t >= NGROUP) return;
    const int m = t & 7;
    const int q = (t >> 3) & (LQ - 1);
    const int n = t >> 17;

    // softmax over the head's 16 logits
    const float* lg = g_attn + (size_t)t * 16;
    float a[16];
    float4 u0 = *(const float4*)(lg + 0),  u1 = *(const float4*)(lg + 4);
    float4 u2 = *(const float4*)(lg + 8),  u3 = *(const float4*)(lg + 12);
    a[0]=u0.x; a[1]=u0.y; a[2]=u0.z; a[3]=u0.w;
    a[4]=u1.x; a[5]=u1.y; a[6]=u1.z; a[7]=u1.w;
    a[8]=u2.x; a[9]=u2.y; a[10]=u2.z; a[11]=u2.w;
    a[12]=u3.x; a[13]=u3.y; a[14]=u3.z; a[15]=u3.w;
    float mx = a[0];
    #pragma unroll
    for (int k = 1; k < 16; k++) mx = fmaxf(mx, a[k]);
    float s = 0.f;
    #pragma unroll
    for (int k = 0; k < 16; k++) { a[k] = expf(a[k] - mx); s += a[k]; }
    const float inv = 1.f / s;

    const float* offp = g_off + (size_t)(n * LQ + q) * CDIM + m * 32;
    const float refx = ((q & 127) + 0.5f) * (1.0f / 128.0f);
    const float refy = ((q >> 7)  + 0.5f) * (1.0f / 128.0f);

    int start = 0;
    #pragma unroll
    for (int l = 0; l < NL; l++) {
        const int W = 128 >> l;
        const float fW = (float)W;
        const int base = n * LIN + start;
        #pragma unroll
        for (int p = 0; p < NP; p++) {
            const int pi = l * NP + p;
            const float ox = offp[pi * 2 + 0];
            const float oy = offp[pi * 2 + 1];
            const float aw = a[p * NP + l] * inv;    // transposed (l,p) pairing

            const float x = refx * fW + ox - 0.5f;
            const float y = refy * fW + oy - 0.5f;
            const float xf = floorf(x), yf = floorf(y);
            const int x0 = (int)xf, y0 = (int)yf;
            const float wx1 = x - xf, wy1 = y - yf;
            const float wx0 = 1.f - wx1, wy0 = 1.f - wy1;

            const bool vx0 = (x0 >= 0) && (x0 < W);
            const bool vx1 = (x0 >= -1) && (x0 < W - 1);
            const bool vy0 = (y0 >= 0) && (y0 < W);
            const bool vy1 = (y0 >= -1) && (y0 < W - 1);

            const int xc0 = min(max(x0, 0), W - 1);
            const int xc1 = min(max(x0 + 1, 0), W - 1);
            const int yc0 = min(max(y0, 0), W - 1);
            const int yc1 = min(max(y0 + 1, 0), W - 1);

            int4 idx;
            idx.x = base + yc0 * W + xc0;
            idx.y = base + yc0 * W + xc1;
            idx.z = base + yc1 * W + xc0;
            idx.w = base + yc1 * W + xc1;
            float4 w;
            w.x = (vy0 && vx0) ? aw * wy0 * wx0 : 0.f;
            w.y = (vy0 && vx1) ? aw * wy0 * wx1 : 0.f;
            w.z = (vy1 && vx0) ? aw * wy1 * wx0 : 0.f;
            w.w = (vy1 && vx1) ? aw * wy1 * wx1 : 0.f;

            g_pidx[pi * NGROUP + t] = idx;
            g_pw  [pi * NGROUP + t] = w;
        }
        start += W * W;
    }
}

// ---------------------------------------------------------------------------
// Lean sampler: pure gather + weighted sum. Warp = (n,q,head-pair);
// half-warp = head, lane's d2 -> channels 2*d2, 2*d2+1 as __half2.
// ---------------------------------------------------------------------------
__global__ __launch_bounds__(256) void sample_kernel()
{
    const int wg   = (blockIdx.x * 256 + threadIdx.x) >> 5;  // (n,q,mp)
    const int lane = threadIdx.x & 31;
    const int mp = wg & 3;
    const int q  = (wg >> 2) & (LQ - 1);
    const int n  = wg >> 16;
    const int m  = mp * 2 + (lane >> 4);
    const int d2 = lane & 15;

    const int bi = ((n * LQ + q) * NH + m);
    const __half* vb = g_value_h + m * 32 + 2 * d2;

    float2 acc = make_float2(0.f, 0.f);
    #pragma unroll
    for (int pi = 0; pi < 16; pi++) {
        const int4   idx = g_pidx[(size_t)pi * NGROUP + bi];
        const float4 w   = g_pw  [(size_t)pi * NGROUP + bi];
        float2 f00 = __half22float2(*(const __half2*)(vb + (size_t)idx.x * CDIM));
        float2 f01 = __half22float2(*(const __half2*)(vb + (size_t)idx.y * CDIM));
        float2 f10 = __half22float2(*(const __half2*)(vb + (size_t)idx.z * CDIM));
        float2 f11 = __half22float2(*(const __half2*)(vb + (size_t)idx.w * CDIM));
        acc.x += w.x * f00.x + w.y * f01.x + w.z * f10.x + w.w * f11.x;
        acc.y += w.x * f00.y + w.y * f01.y + w.z * f10.y + w.w * f11.y;
    }
    *(float2*)(g_sampled + (size_t)(n * LQ + q) * CDIM + m * 32 + 2 * d2) = acc;
}

// ---------------------------------------------------------------------------
// kernel_launch
// ---------------------------------------------------------------------------
extern "C" void kernel_launch(void* const* d_in, const int* in_sizes, int n_in,
                              void* d_out, int out_size)
{
    const float* query         = (const float*)d_in[0];
    const float* input_flatten = (const float*)d_in[2];
    const float* b_off  = (const float*)d_in[6];
    const float* b_attn = (const float*)d_in[8];
    const float* b_val  = (const float*)d_in[10];
    const float* b_out  = (const float*)d_in[12];
    const float* W_off  = (const float*)d_in[5];
    const float* W_attn = (const float*)d_in[7];
    const float* W_val  = (const float*)d_in[9];
    const float* W_out  = (const float*)d_in[11];
    float* out = (float*)d_out;

    __half* p_value_h; float *p_off, *p_attn, *p_sampled;
    cudaGetSymbolAddress((void**)&p_value_h, g_value_h);
    cudaGetSymbolAddress((void**)&p_off,     g_off);
    cudaGetSymbolAddress((void**)&p_attn,    g_attn);
    cudaGetSymbolAddress((void**)&p_sampled, g_sampled);
    __nv_bfloat16 *wv_h, *wv_l, *wu_h, *wu_l;
    cudaGetSymbolAddress((void**)&wv_h, g_wval_hi);  cudaGetSymbolAddress((void**)&wv_l, g_wval_lo);
    cudaGetSymbolAddress((void**)&wu_h, g_wout_hi);  cudaGetSymbolAddress((void**)&wu_l, g_wout_lo);

    cudaFuncSetAttribute(gemm_mma_kernel<false>,
                         cudaFuncAttributeMaxDynamicSharedMemorySize, SMEM_GEMM);
    cudaFuncSetAttribute(gemm_mma_kernel<true>,
                         cudaFuncAttributeMaxDynamicSharedMemorySize, SMEM_GEMM);
    cudaFuncSetAttribute(gemm_q_kernel,
                         cudaFuncAttributeMaxDynamicSharedMemorySize, SMEM_GEMM);

    // 0) weight transpose + split (single launch)
    transpose_all_kernel<<<dim3(256, 4), 256>>>(W_val, W_off, W_attn, W_out);

    // 1) value projection [43520, 256] -> fp16
    gemm_mma_kernel<true><<<dim3((N_BATCH * LIN) / 128, 2), 256, SMEM_GEMM>>>(
        input_flatten, wv_h, wv_l, b_val, p_value_h, 256);
    // 2) merged offset + attn projections [32768 x (256|128)]
    gemm_q_kernel<<<dim3((N_BATCH * LQ) / 128, 3), 256, SMEM_GEMM>>>(
        query, b_off, b_attn, p_off, p_attn);
    // 3) softmax + gather geometry prep
    prep_kernel<<<NGROUP / 256, 256>>>();
    // 4) lean deformable sampling
    sample_kernel<<<(N_BATCH * LQ * 4) / 8, 256>>>();
    // 5) output projection [32768, 256]
    gemm_mma_kernel<false><<<dim3((N_BATCH * LQ) / 128, 2), 256, SMEM_GEMM>>>(
        p_sampled, wu_h, wu_l, b_out, out, 256);
}

// round 9
// speedup vs baseline: 1.4684x; 1.4684x over previous
#include <cuda_runtime.h>
#include <cuda_bf16.h>
#include <cuda_fp16.h>
#include <cstdint>
#include <math.h>

// Problem constants (fixed by the reference setup)
#define N_BATCH 2
#define LQ      16384
#define CDIM    256
#define NH      8
#define NL      4
#define NP      4
#define LIN     21760
#define NGROUP  (N_BATCH*LQ*NH)

// Scratch (device globals; allocation is forbidden)
__device__ __half g_value_h[N_BATCH*LIN*CDIM];   // fp16 projected values
__device__ float  g_off    [N_BATCH*LQ*CDIM];
__device__ float  g_attn   [N_BATCH*LQ*NH*NL*NP];// attn logits (pre-softmax)
__device__ float  g_sampled[N_BATCH*LQ*CDIM];
// Pre-transposed weights, bf16 hi/lo split: [N, K=256] row-major
__device__ __nv_bfloat16 g_wval_hi [CDIM*CDIM], g_wval_lo [CDIM*CDIM];
__device__ __nv_bfloat16 g_woff_hi [CDIM*CDIM], g_woff_lo [CDIM*CDIM];
__device__ __nv_bfloat16 g_wattn_hi[128*CDIM],  g_wattn_lo[128*CDIM];
__device__ __nv_bfloat16 g_wout_hi [CDIM*CDIM], g_wout_lo [CDIM*CDIM];

// ---------------------------------------------------------------------------
// PTX helpers (baseline PTX only — sm_103 non-variant target)
// ---------------------------------------------------------------------------
__device__ __forceinline__ uint32_t smem_u32(const void* p) {
    uint32_t a;
    asm("{ .reg .u64 t; cvta.to.shared.u64 t, %1; cvt.u32.u64 %0, t; }"
        : "=r"(a) : "l"(p));
    return a;
}
__device__ __forceinline__ void ldsm4(uint32_t* r, uint32_t addr) {
    asm volatile("ldmatrix.sync.aligned.m8n8.x4.shared.b16 {%0,%1,%2,%3}, [%4];"
                 : "=r"(r[0]), "=r"(r[1]), "=r"(r[2]), "=r"(r[3]) : "r"(addr));
}
__device__ __forceinline__ void mma16816(float* d, const uint32_t* a, const uint32_t* b) {
    asm volatile(
        "mma.sync.aligned.m16n8k16.row.col.f32.bf16.bf16.f32 "
        "{%0,%1,%2,%3}, {%4,%5,%6,%7}, {%8,%9}, {%0,%1,%2,%3};"
        : "+f"(d[0]), "+f"(d[1]), "+f"(d[2]), "+f"(d[3])
        : "r"(a[0]), "r"(a[1]), "r"(a[2]), "r"(a[3]), "r"(b[0]), "r"(b[1]));
}
#define CP_ASYNC16(dst, src) \
    asm volatile("cp.async.ca.shared.global [%0], [%1], 16;" :: "r"(dst), "l"(src))
#define CP_COMMIT()  asm volatile("cp.async.commit_group;")
#define CP_WAIT0()   asm volatile("cp.async.wait_group 0;" ::: "memory")

// ---------------------------------------------------------------------------
// Fused weight transpose + bf16 hi/lo split (4 weights, one launch)
// ---------------------------------------------------------------------------
__global__ void transpose_all_kernel(
    const float* __restrict__ Wv, const float* __restrict__ Wo,
    const float* __restrict__ Wa, const float* __restrict__ Wu)
{
    const int which = blockIdx.y;
    const int N = (which == 2) ? 128 : 256;
    int idx = blockIdx.x * 256 + threadIdx.x;
    if (idx >= 256 * N) return;
    const float* W = (which == 0) ? Wv : (which == 1) ? Wo : (which == 2) ? Wa : Wu;
    __nv_bfloat16* hi = (which == 0) ? g_wval_hi : (which == 1) ? g_woff_hi
                       : (which == 2) ? g_wattn_hi : g_wout_hi;
    __nv_bfloat16* lo = (which == 0) ? g_wval_lo : (which == 1) ? g_woff_lo
                       : (which == 2) ? g_wattn_lo : g_wout_lo;
    int k = idx / N, n = idx % N;
    float w = W[idx];
    __nv_bfloat16 h = __float2bfloat16(w);
    hi[n * 256 + k] = h;
    lo[n * 256 + k] = __float2bfloat16(w - __bfloat162float(h));
}

// ---------------------------------------------------------------------------
// HMMA GEMM core, bf16x3 split, double-buffered (cp.async B, reg-prefetch A).
// CTA 128x128, BK=32, 8 warps 4x2.
// ---------------------------------------------------------------------------
#define GK       256
#define GBK      32
#define ASTRIDEB 80
#define ABUF     (128 * ASTRIDEB)
#define SMEM_GEMM (8 * ABUF)           // 81920B

template<bool HALF_OUT>
__device__ __forceinline__ void gemm_core(
    const float* __restrict__ A,
    const __nv_bfloat16* __restrict__ Bt_hi,
    const __nv_bfloat16* __restrict__ Bt_lo,
    const float* __restrict__ bias,
    void* __restrict__ Cv, int ldc, int m0, int n0, char* sm)
{
    const uint32_t sb = smem_u32(sm);
    const int tid  = threadIdx.x;
    const int wid  = tid >> 5, lane = tid & 31;
    const int wm   = wid & 3,  wn   = wid >> 2;

    const int frow = tid >> 1;
    const int fkh  = (tid & 1) * 16;

    float acc[2][8][4];
    #pragma unroll
    for (int i = 0; i < 2; i++)
        #pragma unroll
        for (int j = 0; j < 8; j++)
            #pragma unroll
            for (int v = 0; v < 4; v++) acc[i][j][v] = 0.f;

    uint32_t a_addr[2];
    #pragma unroll
    for (int mt = 0; mt < 2; mt++)
        a_addr[mt] = sb + (wm * 32 + mt * 16 + (lane & 15)) * ASTRIDEB
                        + ((lane >> 4) * 8) * 2;
    uint32_t b_addr[4];
    #pragma unroll
    for (int bt = 0; bt < 4; bt++)
        b_addr[bt] = sb + (wn * 64 + bt * 16 + ((lane >> 4) * 8) + (lane & 7)) * ASTRIDEB
                        + (((lane >> 3) & 1) * 8) * 2;

    const float* arow_ptr = A + (size_t)(m0 + frow) * GK + fkh;
    const __nv_bfloat16* bh_ptr = Bt_hi + (size_t)(n0 + frow) * GK + fkh;
    const __nv_bfloat16* bl_ptr = Bt_lo + (size_t)(n0 + frow) * GK + fkh;
    const uint32_t bfill = sb + frow * ASTRIDEB + fkh * 2;

    {
        uint32_t dh = bfill + 4 * ABUF;
        uint32_t dl = dh + ABUF;
        CP_ASYNC16(dh,      bh_ptr);
        CP_ASYNC16(dh + 16, bh_ptr + 8);
        CP_ASYNC16(dl,      bl_ptr);
        CP_ASYNC16(dl + 16, bl_ptr + 8);
        CP_COMMIT();
    }
    float4 va[4];
    #pragma unroll
    for (int j = 0; j < 4; j++) va[j] = ((const float4*)arow_ptr)[j];

    for (int i = 0; i < GK / GBK; i++) {
        const int s = i & 1;
        {
            float v[16];
            #pragma unroll
            for (int j = 0; j < 4; j++) {
                v[j*4+0] = va[j].x; v[j*4+1] = va[j].y;
                v[j*4+2] = va[j].z; v[j*4+3] = va[j].w;
            }
            __nv_bfloat16 h[16], l[16];
            #pragma unroll
            for (int j = 0; j < 16; j++) {
                h[j] = __float2bfloat16(v[j]);
                l[j] = __float2bfloat16(v[j] - __bfloat162float(h[j]));
            }
            char* dh = sm + s * 2 * ABUF + frow * ASTRIDEB + fkh * 2;
            char* dl = dh + ABUF;
            ((uint4*)dh)[0] = ((uint4*)h)[0];  ((uint4*)dh)[1] = ((uint4*)h)[1];
            ((uint4*)dl)[0] = ((uint4*)l)[0];  ((uint4*)dl)[1] = ((uint4*)l)[1];
        }
        if (i < GK / GBK - 1) {
            const float4* nxt = (const float4*)(arow_ptr + (i + 1) * GBK);
            #pragma unroll
            for (int j = 0; j < 4; j++) va[j] = nxt[j];
        }

        CP_WAIT0();
        __syncthreads();

        if (i < GK / GBK - 1) {
            const __nv_bfloat16* sh = bh_ptr + (i + 1) * GBK;
            const __nv_bfloat16* sl = bl_ptr + (i + 1) * GBK;
            uint32_t dh = bfill + 4 * ABUF + (s ^ 1) * 2 * ABUF;
            uint32_t dl = dh + ABUF;
            CP_ASYNC16(dh,      sh);
            CP_ASYNC16(dh + 16, sh + 8);
            CP_ASYNC16(dl,      sl);
            CP_ASYNC16(dl + 16, sl + 8);
            CP_COMMIT();
        }

        const uint32_t aoffS = s * 2 * ABUF;
        const uint32_t boffS = 4 * ABUF + s * 2 * ABUF;
        #pragma unroll
        for (int kk = 0; kk < GBK; kk += 16) {
            const uint32_t ko = kk * 2;
            uint32_t ah[2][4], al[2][4];
            #pragma unroll
            for (int mt = 0; mt < 2; mt++) {
                ldsm4(ah[mt], a_addr[mt] + aoffS + ko);
                ldsm4(al[mt], a_addr[mt] + aoffS + ABUF + ko);
            }
            #pragma unroll
            for (int bt = 0; bt < 4; bt++) {
                uint32_t bh[4], bl[4];
                ldsm4(bh, b_addr[bt] + boffS + ko);
                ldsm4(bl, b_addr[bt] + boffS + ABUF + ko);
                #pragma unroll
                for (int mt = 0; mt < 2; mt++) {
                    float* d0 = acc[mt][bt * 2 + 0];
                    float* d1 = acc[mt][bt * 2 + 1];
                    mma16816(d0, ah[mt], bh + 0);
                    mma16816(d0, ah[mt], bl + 0);
                    mma16816(d0, al[mt], bh + 0);
                    mma16816(d1, ah[mt], bh + 2);
                    mma16816(d1, ah[mt], bl + 2);
                    mma16816(d1, al[mt], bh + 2);
                }
            }
        }
        __syncthreads();
    }

    const int r_in = lane >> 2;
    const int c_in = (lane & 3) * 2;
    #pragma unroll
    for (int mt = 0; mt < 2; mt++) {
        const int rbase = m0 + wm * 32 + mt * 16 + r_in;
        #pragma unroll
        for (int nf = 0; nf < 8; nf++) {
            const int col = n0 + wn * 64 + nf * 8 + c_in;
            const float b0 = bias[col], b1 = bias[col + 1];
            float* d = acc[mt][nf];
            if (HALF_OUT) {
                __half* C = (__half*)Cv;
                *(__half2*)(C + (size_t)rbase       * ldc + col) =
                    __floats2half2_rn(d[0] + b0, d[1] + b1);
                *(__half2*)(C + (size_t)(rbase + 8) * ldc + col) =
                    __floats2half2_rn(d[2] + b0, d[3] + b1);
            } else {
                float* C = (float*)Cv;
                *(float2*)(C + (size_t)rbase       * ldc + col) = make_float2(d[0] + b0, d[1] + b1);
                *(float2*)(C + (size_t)(rbase + 8) * ldc + col) = make_float2(d[2] + b0, d[3] + b1);
            }
        }
    }
}

template<bool HALF_OUT>
__global__ __launch_bounds__(256, 2) void gemm_mma_kernel(
    const float* __restrict__ A,
    const __nv_bfloat16* __restrict__ Bt_hi,
    const __nv_bfloat16* __restrict__ Bt_lo,
    const float* __restrict__ bias,
    void* __restrict__ Cv, int ldc)
{
    extern __shared__ __align__(16) char sm[];
    gemm_core<HALF_OUT>(A, Bt_hi, Bt_lo, bias, Cv, ldc,
                        blockIdx.x * 128, blockIdx.y * 128, sm);
}

// Merged offset + attn projection: grid.y in {0,1} -> g_off cols, {2} -> g_attn
__global__ __launch_bounds__(256, 2) void gemm_q_kernel(
    const float* __restrict__ query,
    const float* __restrict__ b_off, const float* __restrict__ b_attn,
    float* __restrict__ off_out, float* __restrict__ attn_out)
{
    extern __shared__ __align__(16) char sm[];
    const __nv_bfloat16 *Bh, *Bl;
    const float* bias;
    float* C;
    int ldc, n0;
    if (blockIdx.y < 2) {
        Bh = g_woff_hi;  Bl = g_woff_lo;  bias = b_off;
        C = off_out;  ldc = 256;  n0 = blockIdx.y * 128;
    } else {
        Bh = g_wattn_hi; Bl = g_wattn_lo; bias = b_attn;
        C = attn_out; ldc = 128;  n0 = 0;
    }
    gemm_core<false>(query, Bh, Bl, bias, C, ldc, blockIdx.x * 128, n0, sm);
}

// ---------------------------------------------------------------------------
// Fused sampler: softmax + geometry computed ONCE per (head, point) — one
// lane each (warp = head-pair x 16 points) — exchanged via smem, then the
// gather loop does pure loads + FMAs. No global materialization.
//
// Weight pairing: sample at (l,p) is weighted by softmax'd attn[p*4+l]
// (the reference pairs p-major sampled values with l-major weights).
// ---------------------------------------------------------------------------
__global__ __launch_bounds__(256) void fused_sample_kernel()
{
    // [warp][pi*2 + half] interleave -> geometry reads are 2 distinct
    // addresses 16B apart (different banks), broadcast within each half.
    __shared__ __align__(16) int4   sidx[8 * 32];
    __shared__ __align__(16) float4 sw  [8 * 32];

    const int tid  = threadIdx.x;
    const int wid  = tid >> 5, lane = tid & 31;
    const int wg   = blockIdx.x * 8 + wid;      // (n, q, mp)
    const int mp   = wg & 3;
    const int q    = (wg >> 2) & (LQ - 1);
    const int n    = wg >> 16;
    const int half = lane >> 4;
    const int m    = mp * 2 + half;

    // ---- geometry phase: this lane handles point pi for head m
    {
        const int pi = lane & 15;
        const int l = pi >> 2, p = pi & 3;
        const float* offp  = g_off  + (size_t)(n * LQ + q) * CDIM + m * 32;
        const float* attnp = g_attn + ((size_t)(n * LQ + q) * NH + m) * 16;
        const float ox = offp[2 * pi];
        const float oy = offp[2 * pi + 1];
        float lg = attnp[p * 4 + l];            // transposed (l,p) pairing

        // softmax across the 16 lanes of this half-warp
        float mx = lg;
        #pragma unroll
        for (int k = 8; k >= 1; k >>= 1)
            mx = fmaxf(mx, __shfl_xor_sync(0xffffffffu, mx, k, 16));
        float e = expf(lg - mx);
        float s = e;
        #pragma unroll
        for (int k = 8; k >= 1; k >>= 1)
            s += __shfl_xor_sync(0xffffffffu, s, k, 16);
        const float aw = e / s;

        const int W = 128 >> l;
        const int start = (l == 0) ? 0 : (l == 1) ? 16384 : (l == 2) ? 20480 : 21504;
        const float refx = ((q & 127) + 0.5f) * (1.0f / 128.0f);
        const float refy = ((q >> 7)  + 0.5f) * (1.0f / 128.0f);

        const float x = refx * (float)W + ox - 0.5f;
        const float y = refy * (float)W + oy - 0.5f;
        const float xf = floorf(x), yf = floorf(y);
        const int x0 = (int)xf, y0 = (int)yf;
        const float wx1 = x - xf, wy1 = y - yf;
        const float wx0 = 1.f - wx1, wy0 = 1.f - wy1;

        const bool vx0 = (x0 >= 0) && (x0 < W);
        const bool vx1 = (x0 >= -1) && (x0 < W - 1);
        const bool vy0 = (y0 >= 0) && (y0 < W);
        const bool vy1 = (y0 >= -1) && (y0 < W - 1);

        const int xc0 = min(max(x0, 0), W - 1);
        const int xc1 = min(max(x0 + 1, 0), W - 1);
        const int yc0 = min(max(y0, 0), W - 1);
        const int yc1 = min(max(y0 + 1, 0), W - 1);

        // byte offsets into g_value_h, head folded in (row*512 + m*64)
        const int rb = (n * LIN + start) * 512 + m * 64;
        int4 idx;
        idx.x = rb + (yc0 * W + xc0) * 512;
        idx.y = rb + (yc0 * W + xc1) * 512;
        idx.z = rb + (yc1 * W + xc0) * 512;
        idx.w = rb + (yc1 * W + xc1) * 512;
        float4 w;
        w.x = (vy0 && vx0) ? aw * wy0 * wx0 : 0.f;
        w.y = (vy0 && vx1) ? aw * wy0 * wx1 : 0.f;
        w.z = (vy1 && vx0) ? aw * wy1 * wx0 : 0.f;
        w.w = (vy1 && vx1) ? aw * wy1 * wx1 : 0.f;

        sidx[wid * 32 + pi * 2 + half] = idx;
        sw  [wid * 32 + pi * 2 + half] = w;
    }
    __syncwarp();

    // ---- gather phase: lane covers channels 2*d2, 2*d2+1 of head m
    const int d2 = lane & 15;
    const char* vb = (const char*)g_value_h + 4 * d2;
    float2 acc = make_float2(0.f, 0.f);
    #pragma unroll
    for (int pi = 0; pi < 16; pi++) {
        const int4   idx = sidx[wid * 32 + pi * 2 + half];
        const float4 w   = sw  [wid * 32 + pi * 2 + half];
        float2 f00 = __half22float2(*(const __half2*)(vb + idx.x));
        float2 f01 = __half22float2(*(const __half2*)(vb + idx.y));
        float2 f10 = __half22float2(*(const __half2*)(vb + idx.z));
        float2 f11 = __half22float2(*(const __half2*)(vb + idx.w));
        acc.x += w.x * f00.x + w.y * f01.x + w.z * f10.x + w.w * f11.x;
        acc.y += w.x * f00.y + w.y * f01.y + w.z * f10.y + w.w * f11.y;
    }
    *(float2*)(g_sampled + (size_t)(n * LQ + q) * CDIM + m * 32 + 2 * d2) = acc;
}

// ---------------------------------------------------------------------------
// kernel_launch
// ---------------------------------------------------------------------------
extern "C" void kernel_launch(void* const* d_in, const int* in_sizes, int n_in,
                              void* d_out, int out_size)
{
    const float* query         = (const float*)d_in[0];
    const float* input_flatten = (const float*)d_in[2];
    const float* W_off  = (const float*)d_in[5];
    const float* b_off  = (const float*)d_in[6];
    const float* W_attn = (const float*)d_in[7];
    const float* b_attn = (const float*)d_in[8];
    const float* W_val  = (const float*)d_in[9];
    const float* b_val  = (const float*)d_in[10];
    const float* W_out  = (const float*)d_in[11];
    const float* b_out  = (const float*)d_in[12];
    float* out = (float*)d_out;

    __half* p_value_h; float *p_off, *p_attn, *p_sampled;
    cudaGetSymbolAddress((void**)&p_value_h, g_value_h);
    cudaGetSymbolAddress((void**)&p_off,     g_off);
    cudaGetSymbolAddress((void**)&p_attn,    g_attn);
    cudaGetSymbolAddress((void**)&p_sampled, g_sampled);
    __nv_bfloat16 *wv_h, *wv_l, *wu_h, *wu_l;
    cudaGetSymbolAddress((void**)&wv_h, g_wval_hi);  cudaGetSymbolAddress((void**)&wv_l, g_wval_lo);
    cudaGetSymbolAddress((void**)&wu_h, g_wout_hi);  cudaGetSymbolAddress((void**)&wu_l, g_wout_lo);

    cudaFuncSetAttribute(gemm_mma_kernel<false>,
                         cudaFuncAttributeMaxDynamicSharedMemorySize, SMEM_GEMM);
    cudaFuncSetAttribute(gemm_mma_kernel<true>,
                         cudaFuncAttributeMaxDynamicSharedMemorySize, SMEM_GEMM);
    cudaFuncSetAttribute(gemm_q_kernel,
                         cudaFuncAttributeMaxDynamicSharedMemorySize, SMEM_GEMM);

    // 0) weight transpose + split (single launch)
    transpose_all_kernel<<<dim3(256, 4), 256>>>(W_val, W_off, W_attn, W_out);

    // 1) value projection [43520, 256] -> fp16
    gemm_mma_kernel<true><<<dim3((N_BATCH * LIN) / 128, 2), 256, SMEM_GEMM>>>(
        input_flatten, wv_h, wv_l, b_val, p_value_h, 256);
    // 2) merged offset + attn projections [32768 x (256|128)]
    gemm_q_kernel<<<dim3((N_BATCH * LQ) / 128, 3), 256, SMEM_GEMM>>>(
        query, b_off, b_attn, p_off, p_attn);
    // 3) fused softmax + geometry + sampling
    fused_sample_kernel<<<(N_BATCH * LQ * 4) / 8, 256>>>();
    // 4) output projection [32768, 256]
    gemm_mma_kernel<false><<<dim3((N_BATCH * LQ) / 128, 2), 256, SMEM_GEMM>>>(
        p_sampled, wu_h, wu_l, b_out, out, 256);
}

// round 10
// speedup vs baseline: 1.5685x; 1.0682x over previous
#include <cuda_runtime.h>
#include <cuda_bf16.h>
#include <cuda_fp16.h>
#include <cstdint>
#include <math.h>

// Problem constants (fixed by the reference setup)
#define N_BATCH 2
#define LQ      16384
#define CDIM    256
#define NH      8
#define NL      4
#define NP      4
#define LIN     21760
#define NGROUP  (N_BATCH*LQ*NH)

// Scratch (device globals; allocation is forbidden)
__device__ __half g_value_h[N_BATCH*LIN*CDIM];   // fp16 projected values
__device__ float  g_off    [N_BATCH*LQ*CDIM];
__device__ float  g_attn   [N_BATCH*LQ*NH*NL*NP];// attn logits (pre-softmax)
__device__ float  g_sampled[N_BATCH*LQ*CDIM];
// Pre-transposed weights, bf16 hi/lo split: [N, K=256] row-major
__device__ __nv_bfloat16 g_wval_hi [CDIM*CDIM], g_wval_lo [CDIM*CDIM];
__device__ __nv_bfloat16 g_woff_hi [CDIM*CDIM], g_woff_lo [CDIM*CDIM];
__device__ __nv_bfloat16 g_wattn_hi[128*CDIM],  g_wattn_lo[128*CDIM];
__device__ __nv_bfloat16 g_wout_hi [CDIM*CDIM], g_wout_lo [CDIM*CDIM];

// ---------------------------------------------------------------------------
// PTX helpers (baseline PTX only — sm_103 non-variant target)
// ---------------------------------------------------------------------------
__device__ __forceinline__ uint32_t smem_u32(const void* p) {
    uint32_t a;
    asm("{ .reg .u64 t; cvta.to.shared.u64 t, %1; cvt.u32.u64 %0, t; }"
        : "=r"(a) : "l"(p));
    return a;
}
__device__ __forceinline__ void ldsm4(uint32_t* r, uint32_t addr) {
    asm volatile("ldmatrix.sync.aligned.m8n8.x4.shared.b16 {%0,%1,%2,%3}, [%4];"
                 : "=r"(r[0]), "=r"(r[1]), "=r"(r[2]), "=r"(r[3]) : "r"(addr));
}
__device__ __forceinline__ void mma16816(float* d, const uint32_t* a, const uint32_t* b) {
    asm volatile(
        "mma.sync.aligned.m16n8k16.row.col.f32.bf16.bf16.f32 "
        "{%0,%1,%2,%3}, {%4,%5,%6,%7}, {%8,%9}, {%0,%1,%2,%3};"
        : "+f"(d[0]), "+f"(d[1]), "+f"(d[2]), "+f"(d[3])
        : "r"(a[0]), "r"(a[1]), "r"(a[2]), "r"(a[3]), "r"(b[0]), "r"(b[1]));
}
#define CP_ASYNC16(dst, src) \
    asm volatile("cp.async.ca.shared.global [%0], [%1], 16;" :: "r"(dst), "l"(src))
#define CP_COMMIT()  asm volatile("cp.async.commit_group;")
#define CP_WAIT0()   asm volatile("cp.async.wait_group 0;" ::: "memory")

// ---------------------------------------------------------------------------
// Fused weight transpose + bf16 hi/lo split (4 weights, one launch)
// ---------------------------------------------------------------------------
__global__ void transpose_all_kernel(
    const float* __restrict__ Wv, const float* __restrict__ Wo,
    const float* __restrict__ Wa, const float* __restrict__ Wu)
{
    const int which = blockIdx.y;
    const int N = (which == 2) ? 128 : 256;
    int idx = blockIdx.x * 256 + threadIdx.x;
    if (idx >= 256 * N) return;
    const float* W = (which == 0) ? Wv : (which == 1) ? Wo : (which == 2) ? Wa : Wu;
    __nv_bfloat16* hi = (which == 0) ? g_wval_hi : (which == 1) ? g_woff_hi
                       : (which == 2) ? g_wattn_hi : g_wout_hi;
    __nv_bfloat16* lo = (which == 0) ? g_wval_lo : (which == 1) ? g_woff_lo
                       : (which == 2) ? g_wattn_lo : g_wout_lo;
    int k = idx / N, n = idx % N;
    float w = W[idx];
    __nv_bfloat16 h = __float2bfloat16(w);
    hi[n * 256 + k] = h;
    lo[n * 256 + k] = __float2bfloat16(w - __bfloat162float(h));
}

// ---------------------------------------------------------------------------
// HMMA GEMM core, bf16x3 split, double-buffered (cp.async B, reg-prefetch A).
// CTA 128x128, BK=32, 8 warps 4x2.
// ---------------------------------------------------------------------------
#define GK       256
#define GBK      32
#define ASTRIDEB 80
#define ABUF     (128 * ASTRIDEB)
#define SMEM_GEMM (8 * ABUF)           // 81920B

template<bool HALF_OUT>
__device__ __forceinline__ void gemm_core(
    const float* __restrict__ A,
    const __nv_bfloat16* __restrict__ Bt_hi,
    const __nv_bfloat16* __restrict__ Bt_lo,
    const float* __restrict__ bias,
    void* __restrict__ Cv, int ldc, int m0, int n0, char* sm)
{
    const uint32_t sb = smem_u32(sm);
    const int tid  = threadIdx.x;
    const int wid  = tid >> 5, lane = tid & 31;
    const int wm   = wid & 3,  wn   = wid >> 2;

    const int frow = tid >> 1;
    const int fkh  = (tid & 1) * 16;

    float acc[2][8][4];
    #pragma unroll
    for (int i = 0; i < 2; i++)
        #pragma unroll
        for (int j = 0; j < 8; j++)
            #pragma unroll
            for (int v = 0; v < 4; v++) acc[i][j][v] = 0.f;

    uint32_t a_addr[2];
    #pragma unroll
    for (int mt = 0; mt < 2; mt++)
        a_addr[mt] = sb + (wm * 32 + mt * 16 + (lane & 15)) * ASTRIDEB
                        + ((lane >> 4) * 8) * 2;
    uint32_t b_addr[4];
    #pragma unroll
    for (int bt = 0; bt < 4; bt++)
        b_addr[bt] = sb + (wn * 64 + bt * 16 + ((lane >> 4) * 8) + (lane & 7)) * ASTRIDEB
                        + (((lane >> 3) & 1) * 8) * 2;

    const float* arow_ptr = A + (size_t)(m0 + frow) * GK + fkh;
    const __nv_bfloat16* bh_ptr = Bt_hi + (size_t)(n0 + frow) * GK + fkh;
    const __nv_bfloat16* bl_ptr = Bt_lo + (size_t)(n0 + frow) * GK + fkh;
    const uint32_t bfill = sb + frow * ASTRIDEB + fkh * 2;

    {
        uint32_t dh = bfill + 4 * ABUF;
        uint32_t dl = dh + ABUF;
        CP_ASYNC16(dh,      bh_ptr);
        CP_ASYNC16(dh + 16, bh_ptr + 8);
        CP_ASYNC16(dl,      bl_ptr);
        CP_ASYNC16(dl + 16, bl_ptr + 8);
        CP_COMMIT();
    }
    float4 va[4];
    #pragma unroll
    for (int j = 0; j < 4; j++) va[j] = ((const float4*)arow_ptr)[j];

    for (int i = 0; i < GK / GBK; i++) {
        const int s = i & 1;
        {
            float v[16];
            #pragma unroll
            for (int j = 0; j < 4; j++) {
                v[j*4+0] = va[j].x; v[j*4+1] = va[j].y;
                v[j*4+2] = va[j].z; v[j*4+3] = va[j].w;
            }
            __nv_bfloat16 h[16], l[16];
            #pragma unroll
            for (int j = 0; j < 16; j++) {
                h[j] = __float2bfloat16(v[j]);
                l[j] = __float2bfloat16(v[j] - __bfloat162float(h[j]));
            }
            char* dh = sm + s * 2 * ABUF + frow * ASTRIDEB + fkh * 2;
            char* dl = dh + ABUF;
            ((uint4*)dh)[0] = ((uint4*)h)[0];  ((uint4*)dh)[1] = ((uint4*)h)[1];
            ((uint4*)dl)[0] = ((uint4*)l)[0];  ((uint4*)dl)[1] = ((uint4*)l)[1];
        }
        if (i < GK / GBK - 1) {
            const float4* nxt = (const float4*)(arow_ptr + (i + 1) * GBK);
            #pragma unroll
            for (int j = 0; j < 4; j++) va[j] = nxt[j];
        }

        CP_WAIT0();
        __syncthreads();

        if (i < GK / GBK - 1) {
            const __nv_bfloat16* sh = bh_ptr + (i + 1) * GBK;
            const __nv_bfloat16* sl = bl_ptr + (i + 1) * GBK;
            uint32_t dh = bfill + 4 * ABUF + (s ^ 1) * 2 * ABUF;
            uint32_t dl = dh + ABUF;
            CP_ASYNC16(dh,      sh);
            CP_ASYNC16(dh + 16, sh + 8);
            CP_ASYNC16(dl,      sl);
            CP_ASYNC16(dl + 16, sl + 8);
            CP_COMMIT();
        }

        const uint32_t aoffS = s * 2 * ABUF;
        const uint32_t boffS = 4 * ABUF + s * 2 * ABUF;
        #pragma unroll
        for (int kk = 0; kk < GBK; kk += 16) {
            const uint32_t ko = kk * 2;
            uint32_t ah[2][4], al[2][4];
            #pragma unroll
            for (int mt = 0; mt < 2; mt++) {
                ldsm4(ah[mt], a_addr[mt] + aoffS + ko);
                ldsm4(al[mt], a_addr[mt] + aoffS + ABUF + ko);
            }
            #pragma unroll
            for (int bt = 0; bt < 4; bt++) {
                uint32_t bh[4], bl[4];
                ldsm4(bh, b_addr[bt] + boffS + ko);
                ldsm4(bl, b_addr[bt] + boffS + ABUF + ko);
                #pragma unroll
                for (int mt = 0; mt < 2; mt++) {
                    float* d0 = acc[mt][bt * 2 + 0];
                    float* d1 = acc[mt][bt * 2 + 1];
                    mma16816(d0, ah[mt], bh + 0);
                    mma16816(d0, ah[mt], bl + 0);
                    mma16816(d0, al[mt], bh + 0);
                    mma16816(d1, ah[mt], bh + 2);
                    mma16816(d1, ah[mt], bl + 2);
                    mma16816(d1, al[mt], bh + 2);
                }
            }
        }
        __syncthreads();
    }

    const int r_in = lane >> 2;
    const int c_in = (lane & 3) * 2;
    #pragma unroll
    for (int mt = 0; mt < 2; mt++) {
        const int rbase = m0 + wm * 32 + mt * 16 + r_in;
        #pragma unroll
        for (int nf = 0; nf < 8; nf++) {
            const int col = n0 + wn * 64 + nf * 8 + c_in;
            const float b0 = bias[col], b1 = bias[col + 1];
            float* d = acc[mt][nf];
            if (HALF_OUT) {
                __half* C = (__half*)Cv;
                *(__half2*)(C + (size_t)rbase       * ldc + col) =
                    __floats2half2_rn(d[0] + b0, d[1] + b1);
                *(__half2*)(C + (size_t)(rbase + 8) * ldc + col) =
                    __floats2half2_rn(d[2] + b0, d[3] + b1);
            } else {
                float* C = (float*)Cv;
                *(float2*)(C + (size_t)rbase       * ldc + col) = make_float2(d[0] + b0, d[1] + b1);
                *(float2*)(C + (size_t)(rbase + 8) * ldc + col) = make_float2(d[2] + b0, d[3] + b1);
            }
        }
    }
}

template<bool HALF_OUT>
__global__ __launch_bounds__(256, 2) void gemm_mma_kernel(
    const float* __restrict__ A,
    const __nv_bfloat16* __restrict__ Bt_hi,
    const __nv_bfloat16* __restrict__ Bt_lo,
    const float* __restrict__ bias,
    void* __restrict__ Cv, int ldc)
{
    extern __shared__ __align__(16) char sm[];
    gemm_core<HALF_OUT>(A, Bt_hi, Bt_lo, bias, Cv, ldc,
                        blockIdx.x * 128, blockIdx.y * 128, sm);
}

// Merged offset + attn projection: grid.y in {0,1} -> g_off cols, {2} -> g_attn
__global__ __launch_bounds__(256, 2) void gemm_q_kernel(
    const float* __restrict__ query,
    const float* __restrict__ b_off, const float* __restrict__ b_attn,
    float* __restrict__ off_out, float* __restrict__ attn_out)
{
    extern __shared__ __align__(16) char sm[];
    const __nv_bfloat16 *Bh, *Bl;
    const float* bias;
    float* C;
    int ldc, n0;
    if (blockIdx.y < 2) {
        Bh = g_woff_hi;  Bl = g_woff_lo;  bias = b_off;
        C = off_out;  ldc = 256;  n0 = blockIdx.y * 128;
    } else {
        Bh = g_wattn_hi; Bl = g_wattn_lo; bias = b_attn;
        C = attn_out; ldc = 128;  n0 = 0;
    }
    gemm_core<false>(query, Bh, Bl, bias, C, ldc, blockIdx.x * 128, n0, sm);
}

// ---------------------------------------------------------------------------
// Fused sampler v2: warp = (n, q, head-quad). Geometry+softmax computed once
// per (head, point) across lanes (2 items/lane), exchanged via smem; gather
// uses LDG.64 (4 channels/lane) and packed HFMA2 corner weighting with fp32
// cross-point accumulation.
//
// Weight pairing: sample at (l,p) weighted by softmax'd attn[p*4+l]
// (the reference pairs p-major sampled values with l-major weights).
// ---------------------------------------------------------------------------
__global__ __launch_bounds__(256) void fused_sample_kernel()
{
    // [warp][pi*4 + hh]: 4 consecutive 16B entries per pi -> 4 distinct banks,
    // 8-way broadcast within each head's lane group. Conflict-free.
    __shared__ __align__(16) int4   sidx[8 * 64];
    __shared__ __align__(16) float4 sw  [8 * 64];

    const int tid  = threadIdx.x;
    const int wid  = tid >> 5, lane = tid & 31;
    const int wg   = blockIdx.x * 8 + wid;      // (n, q, hq)
    const int hq   = wg & 1;                    // heads hq*4 .. hq*4+3
    const int q    = (wg >> 1) & (LQ - 1);
    const int n    = wg >> 15;
    const int row_q = n * LQ + q;

    const float refx = ((q & 127) + 0.5f) * (1.0f / 128.0f);
    const float refy = ((q >> 7)  + 0.5f) * (1.0f / 128.0f);

    // ---- geometry phase: 2 items per lane; item = (hh, pi)
    #pragma unroll
    for (int it = 0; it < 2; it++) {
        const int hh = (lane >> 4) + it * 2;    // 0,1 then 2,3
        const int pi = lane & 15;
        const int m  = hq * 4 + hh;
        const int l  = pi >> 2, p = pi & 3;

        const float2 off2 = *(const float2*)(g_off + (size_t)row_q * CDIM + m * 32 + 2 * pi);
        float lg = g_attn[((size_t)row_q * NH + m) * 16 + p * 4 + l]; // transposed (l,p)

        // softmax across this head's 16 lanes
        float mx = lg;
        #pragma unroll
        for (int k = 8; k >= 1; k >>= 1)
            mx = fmaxf(mx, __shfl_xor_sync(0xffffffffu, mx, k, 16));
        float e = expf(lg - mx);
        float s = e;
        #pragma unroll
        for (int k = 8; k >= 1; k >>= 1)
            s += __shfl_xor_sync(0xffffffffu, s, k, 16);
        const float aw = e / s;

        const int W = 128 >> l;
        const int start = (l == 0) ? 0 : (l == 1) ? 16384 : (l == 2) ? 20480 : 21504;

        const float x = refx * (float)W + off2.x - 0.5f;
        const float y = refy * (float)W + off2.y - 0.5f;
        const float xf = floorf(x), yf = floorf(y);
        const int x0 = (int)xf, y0 = (int)yf;
        const float wx1 = x - xf, wy1 = y - yf;
        const float wx0 = 1.f - wx1, wy0 = 1.f - wy1;

        const bool vx0 = (x0 >= 0) && (x0 < W);
        const bool vx1 = (x0 >= -1) && (x0 < W - 1);
        const bool vy0 = (y0 >= 0) && (y0 < W);
        const bool vy1 = (y0 >= -1) && (y0 < W - 1);

        const int xc0 = min(max(x0, 0), W - 1);
        const int xc1 = min(max(x0 + 1, 0), W - 1);
        const int yc0 = min(max(y0, 0), W - 1);
        const int yc1 = min(max(y0 + 1, 0), W - 1);

        // byte offsets of value rows (512B/row); head folded in at gather
        const int rb = (n * LIN + start);
        int4 idx;
        idx.x = (rb + yc0 * W + xc0) * 512;
        idx.y = (rb + yc0 * W + xc1) * 512;
        idx.z = (rb + yc1 * W + xc0) * 512;
        idx.w = (rb + yc1 * W + xc1) * 512;
        float4 w;
        w.x = (vy0 && vx0) ? aw * wy0 * wx0 : 0.f;
        w.y = (vy0 && vx1) ? aw * wy0 * wx1 : 0.f;
        w.z = (vy1 && vx0) ? aw * wy1 * wx0 : 0.f;
        w.w = (vy1 && vx1) ? aw * wy1 * wx1 : 0.f;

        sidx[wid * 64 + pi * 4 + hh] = idx;
        sw  [wid * 64 + pi * 4 + hh] = w;
    }
    __syncwarp();

    // ---- gather phase: lane covers 4 channels (d4*4 ..+3) of head m
    const int hh = lane >> 3;                   // 0..3
    const int d4 = lane & 7;                    // 0..7
    const int m  = hq * 4 + hh;
    const char* vb = (const char*)g_value_h + m * 64 + d4 * 8;

    float2 accA = make_float2(0.f, 0.f);        // channels d4*4+0, +1
    float2 accB = make_float2(0.f, 0.f);        // channels d4*4+2, +3
    #pragma unroll
    for (int pi = 0; pi < 16; pi++) {
        const int4   idx = sidx[wid * 64 + pi * 4 + hh];
        const float4 w   = sw  [wid * 64 + pi * 4 + hh];
        uint2 v0 = *(const uint2*)(vb + idx.x);
        uint2 v1 = *(const uint2*)(vb + idx.y);
        uint2 v2 = *(const uint2*)(vb + idx.z);
        uint2 v3 = *(const uint2*)(vb + idx.w);
        const __half2 h00 = __float2half2_rn(w.x);
        const __half2 h01 = __float2half2_rn(w.y);
        const __half2 h10 = __float2half2_rn(w.z);
        const __half2 h11 = __float2half2_rn(w.w);

        __half2 pa = __hmul2(h00, *(__half2*)&v0.x);
        pa = __hfma2(h01, *(__half2*)&v1.x, pa);
        pa = __hfma2(h10, *(__half2*)&v2.x, pa);
        pa = __hfma2(h11, *(__half2*)&v3.x, pa);
        __half2 pb = __hmul2(h00, *(__half2*)&v0.y);
        pb = __hfma2(h01, *(__half2*)&v1.y, pb);
        pb = __hfma2(h10, *(__half2*)&v2.y, pb);
        pb = __hfma2(h11, *(__half2*)&v3.y, pb);

        float2 fa = __half22float2(pa);
        float2 fb = __half22float2(pb);
        accA.x += fa.x; accA.y += fa.y;
        accB.x += fb.x; accB.y += fb.y;
    }
    float4 o = make_float4(accA.x, accA.y, accB.x, accB.y);
    *(float4*)(g_sampled + (size_t)row_q * CDIM + m * 32 + d4 * 4) = o;
}

// ---------------------------------------------------------------------------
// kernel_launch
// ---------------------------------------------------------------------------
extern "C" void kernel_launch(void* const* d_in, const int* in_sizes, int n_in,
                              void* d_out, int out_size)
{
    const float* query         = (const float*)d_in[0];
    const float* input_flatten = (const float*)d_in[2];
    const float* W_off  = (const float*)d_in[5];
    const float* b_off  = (const float*)d_in[6];
    const float* W_attn = (const float*)d_in[7];
    const float* b_attn = (const float*)d_in[8];
    const float* W_val  = (const float*)d_in[9];
    const float* b_val  = (const float*)d_in[10];
    const float* W_out  = (const float*)d_in[11];
    const float* b_out  = (const float*)d_in[12];
    float* out = (float*)d_out;

    __half* p_value_h; float *p_off, *p_attn, *p_sampled;
    cudaGetSymbolAddress((void**)&p_value_h, g_value_h);
    cudaGetSymbolAddress((void**)&p_off,     g_off);
    cudaGetSymbolAddress((void**)&p_attn,    g_attn);
    cudaGetSymbolAddress((void**)&p_sampled, g_sampled);
    __nv_bfloat16 *wv_h, *wv_l, *wu_h, *wu_l;
    cudaGetSymbolAddress((void**)&wv_h, g_wval_hi);  cudaGetSymbolAddress((void**)&wv_l, g_wval_lo);
    cudaGetSymbolAddress((void**)&wu_h, g_wout_hi);  cudaGetSymbolAddress((void**)&wu_l, g_wout_lo);

    cudaFuncSetAttribute(gemm_mma_kernel<false>,
                         cudaFuncAttributeMaxDynamicSharedMemorySize, SMEM_GEMM);
    cudaFuncSetAttribute(gemm_mma_kernel<true>,
                         cudaFuncAttributeMaxDynamicSharedMemorySize, SMEM_GEMM);
    cudaFuncSetAttribute(gemm_q_kernel,
                         cudaFuncAttributeMaxDynamicSharedMemorySize, SMEM_GEMM);

    // 0) weight transpose + split (single launch)
    transpose_all_kernel<<<dim3(256, 4), 256>>>(W_val, W_off, W_attn, W_out);

    // 1) value projection [43520, 256] -> fp16
    gemm_mma_kernel<true><<<dim3((N_BATCH * LIN) / 128, 2), 256, SMEM_GEMM>>>(
        input_flatten, wv_h, wv_l, b_val, p_value_h, 256);
    // 2) merged offset + attn projections [32768 x (256|128)]
    gemm_q_kernel<<<dim3((N_BATCH * LQ) / 128, 3), 256, SMEM_GEMM>>>(
        query, b_off, b_attn, p_off, p_attn);
    // 3) fused softmax + geometry + sampling (4 heads/warp, LDG.64)
    fused_sample_kernel<<<(N_BATCH * LQ * 2) / 8, 256>>>();
    // 4) output projection [32768, 256]
    gemm_mma_kernel<false><<<dim3((N_BATCH * LQ) / 128, 2), 256, SMEM_GEMM>>>(
        p_sampled, wu_h, wu_l, b_out, out, 256);
}